// round 3
// baseline (speedup 1.0000x reference)
#include <cuda_runtime.h>
#include <cstdint>

// ---------------- problem constants ----------------
#define Bb 8
#define Nn 131072          // F*T
#define Dd 40
#define P  48              // augmented row width (40 E + 4 V + 4 zero)
#define CELLS (P*P)        // 2304
#define CPB 37             // chunks per batch -> 296 CTAs = 2 per SM
#define CHUNK 3543
#define RPW 448            // rows per warp
#define NTILES 14          // 448/32
#define SROW 36            // smem row stride (floats): bank=(4g+tig) conflict-free
#define SLAB (48*SROW)     // 1728 floats per warp slab
#define SMEM_BYTES (8*SLAB*4)   // 55296 B
#define K2_BLOCKS 72

// ---------------- device scratch ----------------
__device__ __align__(16) float g_partials[(size_t)Bb * CPB * CELLS];
__device__ float g_blocksums[K2_BLOCKS];

// ---------------- PTX helpers ----------------
__device__ __forceinline__ uint32_t smem_u32(const void* p) {
    uint32_t a;
    asm("{ .reg .u64 t; cvta.to.shared.u64 t, %1; cvt.u32.u64 %0, t; }"
        : "=r"(a) : "l"(p));
    return a;
}

#define CVT_TF32(u, f) asm("cvt.rna.tf32.f32 %0, %1;" : "=r"(u) : "f"(f))
#define STS32(a, v)    asm volatile("st.shared.b32 [%0], %1;" :: "r"(a), "r"(v) : "memory")
#define LDS32(v, a)    asm volatile("ld.shared.b32 %0, [%1];" : "=r"(v) : "r"(a))

// D(16x8) += A(16x8,row) * B(8x8,col), tf32 inputs, f32 accum
#define MMA_TF32(dp, a0, a1, a2, a3, b0, b1) \
    asm volatile("mma.sync.aligned.m16n8k8.row.col.f32.tf32.tf32.f32 " \
        "{%0,%1,%2,%3}, {%4,%5,%6,%7}, {%8,%9}, {%0,%1,%2,%3};" \
        : "+f"((dp)[0]), "+f"((dp)[1]), "+f"((dp)[2]), "+f"((dp)[3]) \
        : "r"(a0), "r"(a1), "r"(a2), "r"(a3), "r"(b0), "r"(b1))

// ============================================================
// Kernel 1: partial Gram G = X^T X per (batch, chunk) via tf32 HMMA.
// Each warp: 14 tiles of 32 rows. smem slab holds X^T (48 features x 32
// rows, stride 36). Lower-triangle tiles only (12 of 18), mirrored in reduce1.
// ============================================================
__global__ __launch_bounds__(256, 2)
void gram_hmma_kernel(const float* __restrict__ E, const float* __restrict__ V)
{
    extern __shared__ float sm[];
    const int tid  = threadIdx.x;
    const int w    = tid >> 5;
    const int lane = tid & 31;
    const int g    = lane >> 2;   // group id 0..7
    const int tig  = lane & 3;    // thread in group
    const int b     = blockIdx.y;
    const int chunk = blockIdx.x;

    // zero feature rows 44..47 in every slab (written nowhere else)
    for (int idx = tid; idx < 8 * 4 * SROW; idx += 256) {
        const int slab = idx / (4 * SROW);
        const int rem  = idx - slab * (4 * SROW);
        sm[slab * SLAB + 44 * SROW + rem] = 0.f;
    }
    __syncthreads();

    const int n_end   = min(Nn, (chunk + 1) * CHUNK);
    const int warp_n0 = chunk * CHUNK + w * RPW;
    const float* Eb = E + (size_t)b * Nn * Dd;
    const float* Vb = V + (size_t)b * Nn * 4;

    const uint32_t smw = smem_u32(sm + w * SLAB);
    uint32_t base[6];
#pragma unroll
    for (int m = 0; m < 6; m++)
        base[m] = smw + (uint32_t)(((m * 8 + g) * SROW + tig) * 4);

    float d[48];
#pragma unroll
    for (int k = 0; k < 48; k++) d[k] = 0.f;

    // kept (lower-triangle-covering) D tiles: mt rows 16mt.., nt cols 8nt..
    const int KMT[12] = {0,0, 1,1,1,1, 2,2,2,2,2,2};
    const int KNT[12] = {0,1, 0,1,2,3, 0,1,2,3,4,5};

    for (int t = 0; t < NTILES; t++) {
        const int n0 = warp_n0 + t * 32;
        __syncwarp();   // previous tile fully consumed

        // ---- stage 32 rows, transposed + tf32-converted ----
#pragma unroll
        for (int i = 0; i < 11; i++) {
            const int q = lane + 32 * i;       // float4 slot
            int k, c; const float* src;
            if (q < 320) { k = q / 10; c = (q - 10 * k) * 4;
                           src = Eb + (size_t)(n0 + k) * Dd + c; }
            else         { k = q - 320; c = 40;
                           src = Vb + (size_t)(n0 + k) * 4; }
            float4 v = make_float4(0.f, 0.f, 0.f, 0.f);
            if (n0 + k < n_end) v = *(const float4*)src;
            uint32_t u[4];
            CVT_TF32(u[0], v.x); CVT_TF32(u[1], v.y);
            CVT_TF32(u[2], v.z); CVT_TF32(u[3], v.w);
#pragma unroll
            for (int j = 0; j < 4; j++) {
                const int ii = (lane + j) & 3;  // rotate to spread banks
                STS32(smw + (uint32_t)(((c + ii) * SROW + k) * 4), u[ii]);
            }
        }
        __syncwarp();

        // ---- 4 k-steps of 8; A-frags and B-frags share registers ----
#pragma unroll
        for (int kk = 0; kk < 4; kk++) {
            uint32_t r[6][2];
#pragma unroll
            for (int m = 0; m < 6; m++) {
                LDS32(r[m][0], base[m] + kk * 32);
                LDS32(r[m][1], base[m] + kk * 32 + 16);
            }
#pragma unroll
            for (int f = 0; f < 12; f++) {
                const int mt = KMT[f], nt = KNT[f];
                MMA_TF32(&d[f * 4],
                         r[2 * mt][0], r[2 * mt + 1][0],
                         r[2 * mt][1], r[2 * mt + 1][1],
                         r[nt][0], r[nt][1]);
            }
        }
    }

    // ---- fold 8 warps -> warp 0 (reuse smem) ----
#pragma unroll 1
    for (int half = 4; half >= 1; half >>= 1) {
        __syncthreads();
        if (w >= half && w < 2 * half) {
            float* dst = sm + ((w - half) * 32 + lane) * 48;
#pragma unroll
            for (int k = 0; k < 48; k++) dst[k] = d[k];
        }
        __syncthreads();
        if (w < half) {
            const float* src2 = sm + (w * 32 + lane) * 48;
#pragma unroll
            for (int k = 0; k < 48; k++) d[k] += src2[k];
        }
    }

    if (w == 0) {
        float* out = &g_partials[(size_t)(b * CPB + chunk) * CELLS];
#pragma unroll
        for (int f = 0; f < 12; f++) {
            const int i0 = 16 * KMT[f] + g;
            const int j0 = 8 * KNT[f] + 2 * tig;
            *(float2*)&out[i0 * P + j0]       = make_float2(d[f*4+0], d[f*4+1]);
            *(float2*)&out[(i0 + 8) * P + j0] = make_float2(d[f*4+2], d[f*4+3]);
        }
    }
}

// ============================================================
// Kernel 2: per-cell chunk reduction + weighted square.
// Mirrors skipped upper-triangle tiles: G symmetric per chunk.
// ============================================================
__global__ __launch_bounds__(256)
void reduce1_kernel()
{
    const int idx = blockIdx.x * 256 + threadIdx.x;
    float v = 0.f;
    if (idx < Bb * CELLS) {
        const int batch = idx / CELLS;
        const int cell  = idx - batch * CELLS;
        const int i = cell / P;
        const int j = cell - i * P;
        const bool kept = (j >> 3) <= 2 * (i >> 4) + 1;   // tile was computed
        const int rc = kept ? (i * P + j) : (j * P + i);
        const float* p = &g_partials[(size_t)batch * CPB * CELLS + rc];
        float s = 0.f;
#pragma unroll 1
        for (int c = 0; c < CPB; c++) s += p[(size_t)c * CELLS];
        const float wgt = ((i < Dd) == (j < Dd)) ? 1.0f : -1.0f;
        v = wgt * s * s;
    }
    __shared__ float red[256];
    red[threadIdx.x] = v;
    __syncthreads();
#pragma unroll
    for (int h = 128; h > 0; h >>= 1) {
        if (threadIdx.x < h) red[threadIdx.x] += red[threadIdx.x + h];
        __syncthreads();
    }
    if (threadIdx.x == 0) g_blocksums[blockIdx.x] = red[0];
}

// ============================================================
// Kernel 3: final scalar.
// ============================================================
__global__ __launch_bounds__(128)
void reduce2_kernel(float* __restrict__ out)
{
    __shared__ float s[128];
    const int t = threadIdx.x;
    s[t] = (t < K2_BLOCKS) ? g_blocksums[t] : 0.f;
    __syncthreads();
#pragma unroll
    for (int h = 64; h > 0; h >>= 1) {
        if (t < h) s[t] += s[t + h];
        __syncthreads();
    }
    if (t == 0) out[0] = s[0] / (float)((size_t)Bb * Nn);
}

// ============================================================
extern "C" void kernel_launch(void* const* d_in, const int* in_sizes, int n_in,
                              void* d_out, int out_size)
{
    const float* E = (const float*)d_in[0];
    const float* V = (const float*)d_in[1];
    if (n_in >= 2 && in_sizes[0] < in_sizes[1]) {
        const float* tmp = E; E = V; V = tmp;
    }

    cudaFuncSetAttribute(gram_hmma_kernel,
                         cudaFuncAttributeMaxDynamicSharedMemorySize, SMEM_BYTES);

    dim3 grid1(CPB, Bb);
    gram_hmma_kernel<<<grid1, 256, SMEM_BYTES>>>(E, V);
    reduce1_kernel<<<K2_BLOCKS, 256>>>();
    reduce2_kernel<<<1, 128>>>((float*)d_out);
}

// round 4
// speedup vs baseline: 2.4848x; 2.4848x over previous
#include <cuda_runtime.h>
#include <cstdint>

// ---------------- problem constants ----------------
#define Bb 8
#define Nn 131072          // F*T
#define Dd 40
#define P  48              // augmented row width (40 E + 4 V + 4 zero)
#define CELLS (P*P)        // 2304
#define CPB 37             // chunks per batch -> 296 CTAs = 2 per SM
#define CHUNK 3543
#define RPW 448            // rows per warp
#define NTILES 14          // 448/32
#define ROWB 224           // staged row stride: 56 floats -> conflict-free frags
#define SSTAGE (32*ROWB)   // 7168 B per stage
#define SMEM_BYTES (8*2*SSTAGE)   // 8 warps x 2 stages = 114688 B
#define K2_BLOCKS 72

// ---------------- device scratch ----------------
__device__ __align__(16) float g_partials[(size_t)Bb * CPB * CELLS];
__device__ float g_blocksums[K2_BLOCKS];

// ---------------- PTX helpers ----------------
__device__ __forceinline__ uint32_t smem_u32(const void* p) {
    uint32_t a;
    asm("{ .reg .u64 t; cvta.to.shared.u64 t, %1; cvt.u32.u64 %0, t; }"
        : "=r"(a) : "l"(p));
    return a;
}

#define CVT_TF32(u, f) asm("cvt.rna.tf32.f32 %0, %1;" : "=r"(u) : "f"(f))
#define LDSF(v, a)     asm volatile("ld.shared.f32 %0, [%1];" : "=f"(v) : "r"(a))
#define CPASYNC(dst, src, sz) \
    asm volatile("cp.async.cg.shared.global [%0], [%1], 16, %2;" \
                 :: "r"(dst), "l"(src), "r"(sz) : "memory")
#define CPCOMMIT() asm volatile("cp.async.commit_group;" ::: "memory")
#define CPWAIT1()  asm volatile("cp.async.wait_group 1;" ::: "memory")
#define CPWAIT0()  asm volatile("cp.async.wait_group 0;" ::: "memory")

// D(16x8) += A(16x8,row) * B(8x8,col), tf32 inputs, f32 accum
#define MMA_TF32(dp, a0, a1, a2, a3, b0, b1) \
    asm volatile("mma.sync.aligned.m16n8k8.row.col.f32.tf32.tf32.f32 " \
        "{%0,%1,%2,%3}, {%4,%5,%6,%7}, {%8,%9}, {%0,%1,%2,%3};" \
        : "+f"((dp)[0]), "+f"((dp)[1]), "+f"((dp)[2]), "+f"((dp)[3]) \
        : "r"(a0), "r"(a1), "r"(a2), "r"(a3), "r"(b0), "r"(b1))

// ---- stage one 32-row tile via cp.async (row-major, raw fp32) ----
// lane handles 11 16B chunks: q<320 -> E (row q/10, 16B-chunk q%10),
// q>=320 -> V (row q-320, at byte 160 of the staged row).
__device__ __forceinline__ void stage_tile(uint32_t sbase,
                                           const float* __restrict__ Eb,
                                           const float* __restrict__ Vb,
                                           int n0, int n_end, int lane)
{
#pragma unroll
    for (int i = 0; i < 11; i++) {
        const int q = lane + 32 * i;
        int r, dst;
        const char* src;
        if (q < 320) {
            r = q / 10;
            const int c16 = q - 10 * r;
            src = (const char*)(Eb + (size_t)(n0 + r) * Dd) + c16 * 16;
            dst = r * ROWB + c16 * 16;
        } else {
            r = q - 320;
            src = (const char*)(Vb + (size_t)(n0 + r) * 4);
            dst = r * ROWB + 160;
        }
        uint32_t sz = 16u;
        if (n0 + r >= n_end) { sz = 0u; src = (const char*)Eb; }
        CPASYNC(sbase + (uint32_t)dst, src, sz);
    }
    CPCOMMIT();
}

// ============================================================
// Kernel 1: partial Gram G = X^T X per (batch, chunk), tf32 HMMA,
// cp.async double-buffered staging. Lower-triangle tiles only.
// ============================================================
__global__ __launch_bounds__(256, 2)
void gram_hmma_kernel(const float* __restrict__ E, const float* __restrict__ V)
{
    extern __shared__ float sm[];
    const int tid  = threadIdx.x;
    const int w    = tid >> 5;
    const int lane = tid & 31;
    const int g    = lane >> 2;   // group id 0..7
    const int tig  = lane & 3;    // thread in group
    const int b     = blockIdx.y;
    const int chunk = blockIdx.x;

    // zero all smem once: guarantees feats 44..47 (+pad) read as 0 forever
    {
        float4 z = make_float4(0.f, 0.f, 0.f, 0.f);
        for (int i = tid; i < SMEM_BYTES / 16; i += 256)
            ((float4*)sm)[i] = z;
    }
    __syncthreads();

    const int n_end   = min(Nn, (chunk + 1) * CHUNK);
    const int warp_n0 = chunk * CHUNK + w * RPW;
    const float* Eb = E + (size_t)b * Nn * Dd;
    const float* Vb = V + (size_t)b * Nn * 4;

    const uint32_t swb = smem_u32(sm) + (uint32_t)(w * 2 * SSTAGE);

    // prologue: stage tiles 0 and 1
    stage_tile(swb,          Eb, Vb, warp_n0,      n_end, lane);
    stage_tile(swb + SSTAGE, Eb, Vb, warp_n0 + 32, n_end, lane);

    float d[48];
#pragma unroll
    for (int k = 0; k < 48; k++) d[k] = 0.f;

    // kept (lower-triangle-covering) D tiles
    const int KMT[12] = {0,0, 1,1,1,1, 2,2,2,2,2,2};
    const int KNT[12] = {0,1, 0,1,2,3, 0,1,2,3,4,5};

    for (int t = 0; t < NTILES; t++) {
        CPWAIT1();
        __syncwarp();

        const uint32_t cb = swb + (uint32_t)((t & 1) * SSTAGE);

#pragma unroll
        for (int kk = 0; kk < 4; kk++) {
            const uint32_t ra = cb + (uint32_t)((kk * 8 + tig) * ROWB + g * 4);
            float f0[6], f1[6];
            uint32_t u0[6], u1[6];
#pragma unroll
            for (int m = 0; m < 6; m++) {
                LDSF(f0[m], ra + m * 32);
                LDSF(f1[m], ra + 4 * ROWB + m * 32);
            }
#pragma unroll
            for (int m = 0; m < 6; m++) { CVT_TF32(u0[m], f0[m]); CVT_TF32(u1[m], f1[m]); }
#pragma unroll
            for (int f = 0; f < 12; f++) {
                const int mt = KMT[f], nt = KNT[f];
                MMA_TF32(&d[f * 4],
                         u0[2 * mt], u0[2 * mt + 1],
                         u1[2 * mt], u1[2 * mt + 1],
                         u0[nt], u1[nt]);
            }
        }
        __syncwarp();   // all lanes done reading before overwrite

        if (t + 2 < NTILES)
            stage_tile(cb, Eb, Vb, warp_n0 + (t + 2) * 32, n_end, lane);
    }

    CPWAIT0();

    // ---- fold 8 warps -> warp 0 (reuse smem) ----
#pragma unroll 1
    for (int half = 4; half >= 1; half >>= 1) {
        __syncthreads();
        if (w >= half && w < 2 * half) {
            float* dst = sm + ((w - half) * 32 + lane) * 48;
#pragma unroll
            for (int k = 0; k < 48; k++) dst[k] = d[k];
        }
        __syncthreads();
        if (w < half) {
            const float* src2 = sm + (w * 32 + lane) * 48;
#pragma unroll
            for (int k = 0; k < 48; k++) d[k] += src2[k];
        }
    }

    if (w == 0) {
        float* out = &g_partials[(size_t)(b * CPB + chunk) * CELLS];
#pragma unroll
        for (int f = 0; f < 12; f++) {
            const int i0 = 16 * KMT[f] + g;
            const int j0 = 8 * KNT[f] + 2 * tig;
            *(float2*)&out[i0 * P + j0]       = make_float2(d[f*4+0], d[f*4+1]);
            *(float2*)&out[(i0 + 8) * P + j0] = make_float2(d[f*4+2], d[f*4+3]);
        }
    }
}

// ============================================================
// Kernel 2: per-cell chunk reduction + weighted square (4-way MLP).
// ============================================================
__global__ __launch_bounds__(256)
void reduce1_kernel()
{
    const int idx = blockIdx.x * 256 + threadIdx.x;
    float v = 0.f;
    if (idx < Bb * CELLS) {
        const int batch = idx / CELLS;
        const int cell  = idx - batch * CELLS;
        const int i = cell / P;
        const int j = cell - i * P;
        const bool kept = (j >> 3) <= 2 * (i >> 4) + 1;   // tile was computed
        const int rc = kept ? (i * P + j) : (j * P + i);
        const float* p = &g_partials[(size_t)batch * CPB * CELLS + rc];
        float s0 = 0.f, s1 = 0.f, s2 = 0.f, s3 = 0.f;
        int c = 0;
#pragma unroll 1
        for (; c + 4 <= CPB; c += 4) {
            s0 += p[(size_t)(c + 0) * CELLS];
            s1 += p[(size_t)(c + 1) * CELLS];
            s2 += p[(size_t)(c + 2) * CELLS];
            s3 += p[(size_t)(c + 3) * CELLS];
        }
        for (; c < CPB; c++) s0 += p[(size_t)c * CELLS];
        const float s = (s0 + s1) + (s2 + s3);
        const float wgt = ((i < Dd) == (j < Dd)) ? 1.0f : -1.0f;
        v = wgt * s * s;
    }
    __shared__ float red[256];
    red[threadIdx.x] = v;
    __syncthreads();
#pragma unroll
    for (int h = 128; h > 0; h >>= 1) {
        if (threadIdx.x < h) red[threadIdx.x] += red[threadIdx.x + h];
        __syncthreads();
    }
    if (threadIdx.x == 0) g_blocksums[blockIdx.x] = red[0];
}

// ============================================================
// Kernel 3: final scalar.
// ============================================================
__global__ __launch_bounds__(128)
void reduce2_kernel(float* __restrict__ out)
{
    __shared__ float s[128];
    const int t = threadIdx.x;
    s[t] = (t < K2_BLOCKS) ? g_blocksums[t] : 0.f;
    __syncthreads();
#pragma unroll
    for (int h = 64; h > 0; h >>= 1) {
        if (t < h) s[t] += s[t + h];
        __syncthreads();
    }
    if (t == 0) out[0] = s[0] / (float)((size_t)Bb * Nn);
}

// ============================================================
extern "C" void kernel_launch(void* const* d_in, const int* in_sizes, int n_in,
                              void* d_out, int out_size)
{
    const float* E = (const float*)d_in[0];
    const float* V = (const float*)d_in[1];
    if (n_in >= 2 && in_sizes[0] < in_sizes[1]) {
        const float* tmp = E; E = V; V = tmp;
    }

    cudaFuncSetAttribute(gram_hmma_kernel,
                         cudaFuncAttributeMaxDynamicSharedMemorySize, SMEM_BYTES);

    dim3 grid1(CPB, Bb);
    gram_hmma_kernel<<<grid1, 256, SMEM_BYTES>>>(E, V);
    reduce1_kernel<<<K2_BLOCKS, 256>>>();
    reduce2_kernel<<<1, 128>>>((float*)d_out);
}

// round 5
// speedup vs baseline: 2.5289x; 1.0177x over previous
#include <cuda_runtime.h>
#include <cstdint>

// ---------------- problem constants ----------------
#define Bb 8
#define Nn 131072          // F*T
#define Dd 40
#define P  48              // augmented row width (40 E + 4 V + 4 zero)
#define CELLS (P*P)        // 2304
#define CPB 37             // chunks per batch -> 296 CTAs = 2 per SM
#define CPBP 40            // padded chunk stride (floats) for 16B alignment
#define CHUNK 3543
#define RPW 448            // rows per warp
#define TROWS 16           // rows per tile
#define NTILES 28          // 448/16
#define ROWB 224           // staged row stride (56 floats) -> conflict-free frags
#define SSTAGE (TROWS*ROWB)        // 3584 B per stage
#define STAGES 4
#define SMEM_BYTES (8*STAGES*SSTAGE)   // 114688 B -> 2 CTAs/SM
#define K2_BLOCKS 72

// ---------------- device scratch ----------------
// layout: g_partials[(cell*Bb + b)*CPBP + chunk]  (cell = i*P + j)
__device__ __align__(16) float g_partials[(size_t)CELLS * Bb * CPBP];
__device__ float g_blocksums[K2_BLOCKS];

// ---------------- PTX helpers ----------------
__device__ __forceinline__ uint32_t smem_u32(const void* p) {
    uint32_t a;
    asm("{ .reg .u64 t; cvta.to.shared.u64 t, %1; cvt.u32.u64 %0, t; }"
        : "=r"(a) : "l"(p));
    return a;
}

#define CVT_TF32(u, f) asm("cvt.rna.tf32.f32 %0, %1;" : "=r"(u) : "f"(f))
#define LDSF(v, a)     asm volatile("ld.shared.f32 %0, [%1];" : "=f"(v) : "r"(a))
#define CPASYNC(dst, src, sz) \
    asm volatile("cp.async.cg.shared.global [%0], [%1], 16, %2;" \
                 :: "r"(dst), "l"(src), "r"(sz) : "memory")
#define CPCOMMIT() asm volatile("cp.async.commit_group;" ::: "memory")
#define CPWAIT2()  asm volatile("cp.async.wait_group 2;" ::: "memory")
#define CPWAIT1()  asm volatile("cp.async.wait_group 1;" ::: "memory")
#define CPWAIT0()  asm volatile("cp.async.wait_group 0;" ::: "memory")

// D(16x8) += A(16x8,row) * B(8x8,col), tf32 inputs, f32 accum
#define MMA_TF32(dp, a0, a1, a2, a3, b0, b1) \
    asm volatile("mma.sync.aligned.m16n8k8.row.col.f32.tf32.tf32.f32 " \
        "{%0,%1,%2,%3}, {%4,%5,%6,%7}, {%8,%9}, {%0,%1,%2,%3};" \
        : "+f"((dp)[0]), "+f"((dp)[1]), "+f"((dp)[2]), "+f"((dp)[3]) \
        : "r"(a0), "r"(a1), "r"(a2), "r"(a3), "r"(b0), "r"(b1))

// ---- stage one 16-row tile via cp.async (row-major raw fp32) ----
// 176 16B-slots: q<160 -> E (row q/10, chunk q%10), q>=160 -> V (row q-160).
// Out-of-range rows use src-size 0 => cp.async zero-fills the 16B.
__device__ __forceinline__ void stage_tile(uint32_t sbase,
                                           const float* __restrict__ Eb,
                                           const float* __restrict__ Vb,
                                           int n0, int n_end, int lane)
{
#pragma unroll
    for (int i = 0; i < 6; i++) {
        const int q = lane + 32 * i;
        if (q < 176) {
            int r, dst;
            const char* src;
            if (q < 160) {
                r = q / 10;
                const int c16 = q - 10 * r;
                src = (const char*)(Eb + (size_t)(n0 + r) * Dd) + c16 * 16;
                dst = r * ROWB + c16 * 16;
            } else {
                r = q - 160;
                src = (const char*)(Vb + (size_t)(n0 + r) * 4);
                dst = r * ROWB + 160;
            }
            uint32_t sz = 16u;
            if (n0 + r >= n_end) { sz = 0u; src = (const char*)Eb; }
            CPASYNC(sbase + (uint32_t)dst, src, sz);
        }
    }
    CPCOMMIT();
}

// ============================================================
// Kernel 1: partial Gram G = X^T X per (batch, chunk), tf32 HMMA,
// 4-stage cp.async pipeline (16-row tiles). Lower-triangle tiles only.
// ============================================================
__global__ __launch_bounds__(256, 2)
void gram_hmma_kernel(const float* __restrict__ E, const float* __restrict__ V)
{
    extern __shared__ float sm[];
    const int tid  = threadIdx.x;
    const int w    = tid >> 5;
    const int lane = tid & 31;
    const int g    = lane >> 2;   // group id 0..7
    const int tig  = lane & 3;    // thread in group
    const int b     = blockIdx.y;
    const int chunk = blockIdx.x;

    // zero all smem once: feats 44..47 (+pad bytes 176..223) read as 0 forever
    {
        float4 z = make_float4(0.f, 0.f, 0.f, 0.f);
        for (int i = tid; i < SMEM_BYTES / 16; i += 256)
            ((float4*)sm)[i] = z;
    }
    __syncthreads();

    const int n_end   = min(Nn, (chunk + 1) * CHUNK);
    const int warp_n0 = chunk * CHUNK + w * RPW;
    const float* Eb = E + (size_t)b * Nn * Dd;
    const float* Vb = V + (size_t)b * Nn * 4;

    const uint32_t swb = smem_u32(sm) + (uint32_t)(w * STAGES * SSTAGE);

    // prologue: stage tiles 0..2
    stage_tile(swb,              Eb, Vb, warp_n0,             n_end, lane);
    stage_tile(swb + SSTAGE,     Eb, Vb, warp_n0 + TROWS,     n_end, lane);
    stage_tile(swb + 2 * SSTAGE, Eb, Vb, warp_n0 + 2 * TROWS, n_end, lane);

    float d[48];
#pragma unroll
    for (int k = 0; k < 48; k++) d[k] = 0.f;

    // kept (lower-triangle-covering) D tiles
    const int KMT[12] = {0,0, 1,1,1,1, 2,2,2,2,2,2};
    const int KNT[12] = {0,1, 0,1,2,3, 0,1,2,3,4,5};

    for (int t = 0; t < NTILES; t++) {
        // tail-aware wait: tile t's group MUST be complete
        if (t + 2 < NTILES)      CPWAIT2();
        else if (t + 1 < NTILES) CPWAIT1();
        else                     CPWAIT0();
        __syncwarp();

        const uint32_t cb = swb + (uint32_t)((t & 3) * SSTAGE);

#pragma unroll
        for (int kk = 0; kk < 2; kk++) {
            const uint32_t ra = cb + (uint32_t)((kk * 8 + tig) * ROWB + g * 4);
            float f0[6], f1[6];
            uint32_t u0[6], u1[6];
#pragma unroll
            for (int m = 0; m < 6; m++) {
                LDSF(f0[m], ra + m * 32);
                LDSF(f1[m], ra + 4 * ROWB + m * 32);
            }
#pragma unroll
            for (int m = 0; m < 6; m++) { CVT_TF32(u0[m], f0[m]); CVT_TF32(u1[m], f1[m]); }
#pragma unroll
            for (int f = 0; f < 12; f++) {
                const int mt = KMT[f], nt = KNT[f];
                MMA_TF32(&d[f * 4],
                         u0[2 * mt], u0[2 * mt + 1],
                         u1[2 * mt], u1[2 * mt + 1],
                         u0[nt], u1[nt]);
            }
        }
        __syncwarp();   // all lanes done reading buf (t-1 & 3) targets

        if (t + 3 < NTILES)
            stage_tile(swb + (uint32_t)(((t + 3) & 3) * SSTAGE),
                       Eb, Vb, warp_n0 + (t + 3) * TROWS, n_end, lane);
    }

    CPWAIT0();

    // ---- fold 8 warps -> warp 0 (reuse smem) ----
#pragma unroll 1
    for (int half = 4; half >= 1; half >>= 1) {
        __syncthreads();
        if (w >= half && w < 2 * half) {
            float* dst = sm + ((w - half) * 32 + lane) * 48;
#pragma unroll
            for (int k = 0; k < 48; k++) dst[k] = d[k];
        }
        __syncthreads();
        if (w < half) {
            const float* src2 = sm + (w * 32 + lane) * 48;
#pragma unroll
            for (int k = 0; k < 48; k++) d[k] += src2[k];
        }
    }

    if (w == 0) {
#pragma unroll
        for (int f = 0; f < 12; f++) {
            const int i0 = 16 * KMT[f] + g;
            const int j0 = 8 * KNT[f] + 2 * tig;
#pragma unroll
            for (int h = 0; h < 2; h++) {    // rows i0, i0+8
                const int cell0 = (i0 + 8 * h) * P + j0;
                g_partials[(size_t)(cell0 * Bb + b) * CPBP + chunk]       = d[f*4 + 2*h];
                g_partials[(size_t)((cell0 + 1) * Bb + b) * CPBP + chunk] = d[f*4 + 2*h + 1];
            }
        }
    }
}

// ============================================================
// Kernel 2: per-(cell,batch) chunk reduction + weighted square.
// Contiguous 37-float rows (float4 x9 + 1). Mirrors skipped tiles.
// ============================================================
__global__ __launch_bounds__(256)
void reduce1_kernel()
{
    const int idx = blockIdx.x * 256 + threadIdx.x;   // idx = cell*Bb + b
    float v = 0.f;
    if (idx < Bb * CELLS) {
        const int cell = idx >> 3;
        const int b    = idx & 7;
        const int i = cell / P;
        const int j = cell - i * P;
        const bool kept = (j >> 3) <= 2 * (i >> 4) + 1;   // tile was computed
        const int rcell = kept ? cell : (j * P + i);
        const float4* p = (const float4*)&g_partials[(size_t)(rcell * Bb + b) * CPBP];
        float4 a0 = p[0], a1 = p[1], a2 = p[2], a3 = p[3], a4 = p[4];
        float4 a5 = p[5], a6 = p[6], a7 = p[7], a8 = p[8];
        float s = ((a0.x + a0.y) + (a0.z + a0.w)) + ((a1.x + a1.y) + (a1.z + a1.w))
                + ((a2.x + a2.y) + (a2.z + a2.w)) + ((a3.x + a3.y) + (a3.z + a3.w))
                + ((a4.x + a4.y) + (a4.z + a4.w)) + ((a5.x + a5.y) + (a5.z + a5.w))
                + ((a6.x + a6.y) + (a6.z + a6.w)) + ((a7.x + a7.y) + (a7.z + a7.w))
                + ((a8.x + a8.y) + (a8.z + a8.w))
                + ((const float*)p)[36];
        const float wgt = ((i < Dd) == (j < Dd)) ? 1.0f : -1.0f;
        v = wgt * s * s;
    }
    __shared__ float red[256];
    red[threadIdx.x] = v;
    __syncthreads();
#pragma unroll
    for (int h = 128; h > 0; h >>= 1) {
        if (threadIdx.x < h) red[threadIdx.x] += red[threadIdx.x + h];
        __syncthreads();
    }
    if (threadIdx.x == 0) g_blocksums[blockIdx.x] = red[0];
}

// ============================================================
// Kernel 3: final scalar.
// ============================================================
__global__ __launch_bounds__(128)
void reduce2_kernel(float* __restrict__ out)
{
    __shared__ float s[128];
    const int t = threadIdx.x;
    s[t] = (t < K2_BLOCKS) ? g_blocksums[t] : 0.f;
    __syncthreads();
#pragma unroll
    for (int h = 64; h > 0; h >>= 1) {
        if (t < h) s[t] += s[t + h];
        __syncthreads();
    }
    if (t == 0) out[0] = s[0] / (float)((size_t)Bb * Nn);
}

// ============================================================
extern "C" void kernel_launch(void* const* d_in, const int* in_sizes, int n_in,
                              void* d_out, int out_size)
{
    const float* E = (const float*)d_in[0];
    const float* V = (const float*)d_in[1];
    if (n_in >= 2 && in_sizes[0] < in_sizes[1]) {
        const float* tmp = E; E = V; V = tmp;
    }

    cudaFuncSetAttribute(gram_hmma_kernel,
                         cudaFuncAttributeMaxDynamicSharedMemorySize, SMEM_BYTES);

    dim3 grid1(CPB, Bb);
    gram_hmma_kernel<<<grid1, 256, SMEM_BYTES>>>(E, V);
    reduce1_kernel<<<K2_BLOCKS, 256>>>();
    reduce2_kernel<<<1, 128>>>((float*)d_out);
}

// round 6
// speedup vs baseline: 2.5762x; 1.0187x over previous
#include <cuda_runtime.h>
#include <cstdint>

// ---------------- problem constants ----------------
#define Bb 8
#define Nn 131072          // F*T
#define Dd 40
#define P  48              // augmented row width (40 E + 4 V + 4 zero)
#define CELLS (P*P)        // 2304
#define CPB 37             // chunks per batch -> 296 CTAs = 2 per SM
#define CPBP 40            // padded chunk stride (floats) for 16B alignment
#define CHUNK 3543
#define RPW 448            // rows per warp
#define TROWS 32           // rows per tile
#define NTILES 14          // 448/32
#define ROWB 224           // staged row stride (56 floats) -> conflict-free frags
#define SSTAGE (TROWS*ROWB)        // 7168 B per stage
#define STAGES 2
#define SMEM_BYTES (8*STAGES*SSTAGE)   // 114688 B -> 2 CTAs/SM
#define K2_BLOCKS 72

// ---------------- device scratch ----------------
// layout: g_partials[(cell*Bb + b)*CPBP + chunk]  (cell = i*P + j)
__device__ __align__(16) float g_partials[(size_t)CELLS * Bb * CPBP];
__device__ float g_blocksums[K2_BLOCKS];

// ---------------- PTX helpers ----------------
__device__ __forceinline__ uint32_t smem_u32(const void* p) {
    uint32_t a;
    asm("{ .reg .u64 t; cvta.to.shared.u64 t, %1; cvt.u32.u64 %0, t; }"
        : "=r"(a) : "l"(p));
    return a;
}

#define CVT_TF32(u, f) asm("cvt.rna.tf32.f32 %0, %1;" : "=r"(u) : "f"(f))
#define LDSF(v, a)     asm volatile("ld.shared.f32 %0, [%1];" : "=f"(v) : "r"(a))
#define CPASYNC(dst, src, sz) \
    asm volatile("cp.async.cg.shared.global [%0], [%1], 16, %2;" \
                 :: "r"(dst), "l"(src), "r"(sz) : "memory")
#define CPCOMMIT() asm volatile("cp.async.commit_group;" ::: "memory")
#define CPWAIT1()  asm volatile("cp.async.wait_group 1;" ::: "memory")
#define CPWAIT0()  asm volatile("cp.async.wait_group 0;" ::: "memory")

// D(16x8) += A(16x8,row) * B(8x8,col), tf32 inputs, f32 accum
#define MMA_TF32(dp, a0, a1, a2, a3, b0, b1) \
    asm volatile("mma.sync.aligned.m16n8k8.row.col.f32.tf32.tf32.f32 " \
        "{%0,%1,%2,%3}, {%4,%5,%6,%7}, {%8,%9}, {%0,%1,%2,%3};" \
        : "+f"((dp)[0]), "+f"((dp)[1]), "+f"((dp)[2]), "+f"((dp)[3]) \
        : "r"(a0), "r"(a1), "r"(a2), "r"(a3), "r"(b0), "r"(b1))

// ---- stage one 32-row tile via cp.async (row-major raw fp32) ----
// E block for the tile is CONTIGUOUS in gmem: src offset = q*16.
// dst = q*16 + (q/10)*64 (row pad). V block contiguous too.
// Rows >= nrem zero-fill via src-size 0 (src clamped to a valid address).
__device__ __forceinline__ void stage_tile(uint32_t sbase,
                                           const char* __restrict__ Ebase,
                                           const char* __restrict__ Vbase,
                                           int nrem, int lane)
{
#pragma unroll
    for (int i = 0; i < 10; i++) {          // E: q = lane + 32i in [0,320)
        const int q = lane + 32 * i;
        const int r = q / 10;
        const uint32_t dst = (uint32_t)(q * 16 + r * 64);
        uint32_t sz = 16u;
        const char* src = Ebase + q * 16;
        if (r >= nrem) { sz = 0u; src = Ebase; }
        CPASYNC(sbase + dst, src, sz);
    }
    {                                       // V: one 16B row per lane
        const uint32_t dst = (uint32_t)(lane * ROWB + 160);
        uint32_t sz = 16u;
        const char* src = Vbase + lane * 16;
        if (lane >= nrem) { sz = 0u; src = Vbase; }
        CPASYNC(sbase + dst, src, sz);
    }
    CPCOMMIT();
}

// ============================================================
// Kernel 1: partial Gram G = X^T X per (batch, chunk), tf32 HMMA,
// 2-stage cp.async pipeline, 32-row tiles. Lower-triangle tiles only.
// ============================================================
__global__ __launch_bounds__(256, 2)
void gram_hmma_kernel(const float* __restrict__ E, const float* __restrict__ V)
{
    extern __shared__ float sm[];
    const int tid  = threadIdx.x;
    const int w    = tid >> 5;
    const int lane = tid & 31;
    const int g    = lane >> 2;   // group id 0..7
    const int tig  = lane & 3;    // thread in group
    const int b     = blockIdx.y;
    const int chunk = blockIdx.x;

    // zero all smem once: feats 44..47 (+pad bytes) read as 0 forever
    {
        float4 z = make_float4(0.f, 0.f, 0.f, 0.f);
        for (int i = tid; i < SMEM_BYTES / 16; i += 256)
            ((float4*)sm)[i] = z;
    }
    __syncthreads();

    const int n_end   = min(Nn, (chunk + 1) * CHUNK);
    const int warp_n0 = chunk * CHUNK + w * RPW;
    const char* Eb = (const char*)(E + (size_t)b * Nn * Dd) + (size_t)warp_n0 * 160;
    const char* Vb = (const char*)(V + (size_t)b * Nn * 4) + (size_t)warp_n0 * 16;

    const uint32_t swb = smem_u32(sm) + (uint32_t)(w * STAGES * SSTAGE);

    // prologue: stage tiles 0 and 1
    stage_tile(swb,          Eb,                Vb,               n_end - warp_n0,         lane);
    stage_tile(swb + SSTAGE, Eb + TROWS * 160,  Vb + TROWS * 16,  n_end - warp_n0 - TROWS, lane);

    float d[48];
#pragma unroll
    for (int k = 0; k < 48; k++) d[k] = 0.f;

    // kept (lower-triangle-covering) D tiles
    const int KMT[12] = {0,0, 1,1,1,1, 2,2,2,2,2,2};
    const int KNT[12] = {0,1, 0,1,2,3, 0,1,2,3,4,5};

    for (int t = 0; t < NTILES; t++) {
        // tail-aware wait: tile t's group MUST be complete
        if (t + 1 < NTILES) CPWAIT1();
        else                CPWAIT0();
        __syncwarp();

        const uint32_t cb = swb + (uint32_t)((t & 1) * SSTAGE);

#pragma unroll
        for (int kk = 0; kk < 4; kk++) {
            const uint32_t ra = cb + (uint32_t)((kk * 8 + tig) * ROWB + g * 4);
            float f0[6], f1[6];
            uint32_t u0[6], u1[6];
#pragma unroll
            for (int m = 0; m < 6; m++) {
                LDSF(f0[m], ra + m * 32);
                LDSF(f1[m], ra + 4 * ROWB + m * 32);
            }
#pragma unroll
            for (int m = 0; m < 6; m++) { CVT_TF32(u0[m], f0[m]); CVT_TF32(u1[m], f1[m]); }
#pragma unroll
            for (int f = 0; f < 12; f++) {
                const int mt = KMT[f], nt = KNT[f];
                MMA_TF32(&d[f * 4],
                         u0[2 * mt], u0[2 * mt + 1],
                         u1[2 * mt], u1[2 * mt + 1],
                         u0[nt], u1[nt]);
            }
        }
        __syncwarp();   // all lanes done reading before overwrite

        if (t + 2 < NTILES)
            stage_tile(cb, Eb + (size_t)(t + 2) * TROWS * 160,
                           Vb + (size_t)(t + 2) * TROWS * 16,
                           n_end - warp_n0 - (t + 2) * TROWS, lane);
    }

    CPWAIT0();

    // ---- fold 8 warps -> warp 0 (reuse smem) ----
#pragma unroll 1
    for (int half = 4; half >= 1; half >>= 1) {
        __syncthreads();
        if (w >= half && w < 2 * half) {
            float* dst = sm + ((w - half) * 32 + lane) * 48;
#pragma unroll
            for (int k = 0; k < 48; k++) dst[k] = d[k];
        }
        __syncthreads();
        if (w < half) {
            const float* src2 = sm + (w * 32 + lane) * 48;
#pragma unroll
            for (int k = 0; k < 48; k++) d[k] += src2[k];
        }
    }

    if (w == 0) {
#pragma unroll
        for (int f = 0; f < 12; f++) {
            const int i0 = 16 * KMT[f] + g;
            const int j0 = 8 * KNT[f] + 2 * tig;
#pragma unroll
            for (int h = 0; h < 2; h++) {    // rows i0, i0+8
                const int cell0 = (i0 + 8 * h) * P + j0;
                g_partials[(size_t)(cell0 * Bb + b) * CPBP + chunk]       = d[f*4 + 2*h];
                g_partials[(size_t)((cell0 + 1) * Bb + b) * CPBP + chunk] = d[f*4 + 2*h + 1];
            }
        }
    }
}

// ============================================================
// Kernel 2: per-(cell,batch) chunk reduction + weighted square.
// Contiguous 37-float rows (float4 x9 + 1). Mirrors skipped tiles.
// ============================================================
__global__ __launch_bounds__(256)
void reduce1_kernel()
{
    const int idx = blockIdx.x * 256 + threadIdx.x;   // idx = cell*Bb + b
    float v = 0.f;
    if (idx < Bb * CELLS) {
        const int cell = idx >> 3;
        const int b    = idx & 7;
        const int i = cell / P;
        const int j = cell - i * P;
        const bool kept = (j >> 3) <= 2 * (i >> 4) + 1;   // tile was computed
        const int rcell = kept ? cell : (j * P + i);
        const float4* p = (const float4*)&g_partials[(size_t)(rcell * Bb + b) * CPBP];
        float4 a0 = p[0], a1 = p[1], a2 = p[2], a3 = p[3], a4 = p[4];
        float4 a5 = p[5], a6 = p[6], a7 = p[7], a8 = p[8];
        float s = ((a0.x + a0.y) + (a0.z + a0.w)) + ((a1.x + a1.y) + (a1.z + a1.w))
                + ((a2.x + a2.y) + (a2.z + a2.w)) + ((a3.x + a3.y) + (a3.z + a3.w))
                + ((a4.x + a4.y) + (a4.z + a4.w)) + ((a5.x + a5.y) + (a5.z + a5.w))
                + ((a6.x + a6.y) + (a6.z + a6.w)) + ((a7.x + a7.y) + (a7.z + a7.w))
                + ((a8.x + a8.y) + (a8.z + a8.w))
                + ((const float*)p)[36];
        const float wgt = ((i < Dd) == (j < Dd)) ? 1.0f : -1.0f;
        v = wgt * s * s;
    }
    __shared__ float red[256];
    red[threadIdx.x] = v;
    __syncthreads();
#pragma unroll
    for (int h = 128; h > 0; h >>= 1) {
        if (threadIdx.x < h) red[threadIdx.x] += red[threadIdx.x + h];
        __syncthreads();
    }
    if (threadIdx.x == 0) g_blocksums[blockIdx.x] = red[0];
}

// ============================================================
// Kernel 3: final scalar.
// ============================================================
__global__ __launch_bounds__(128)
void reduce2_kernel(float* __restrict__ out)
{
    __shared__ float s[128];
    const int t = threadIdx.x;
    s[t] = (t < K2_BLOCKS) ? g_blocksums[t] : 0.f;
    __syncthreads();
#pragma unroll
    for (int h = 64; h > 0; h >>= 1) {
        if (t < h) s[t] += s[t + h];
        __syncthreads();
    }
    if (t == 0) out[0] = s[0] / (float)((size_t)Bb * Nn);
}

// ============================================================
extern "C" void kernel_launch(void* const* d_in, const int* in_sizes, int n_in,
                              void* d_out, int out_size)
{
    const float* E = (const float*)d_in[0];
    const float* V = (const float*)d_in[1];
    if (n_in >= 2 && in_sizes[0] < in_sizes[1]) {
        const float* tmp = E; E = V; V = tmp;
    }

    cudaFuncSetAttribute(gram_hmma_kernel,
                         cudaFuncAttributeMaxDynamicSharedMemorySize, SMEM_BYTES);

    dim3 grid1(CPB, Bb);
    gram_hmma_kernel<<<grid1, 256, SMEM_BYTES>>>(E, V);
    reduce1_kernel<<<K2_BLOCKS, 256>>>();
    reduce2_kernel<<<1, 128>>>((float*)d_out);
}